// round 1
// baseline (speedup 1.0000x reference)
#include <cuda_runtime.h>

// Problem constants
constexpr int CB = 4;      // batch
constexpr int CN = 2048;   // query seq
constexpr int CM = 2048;   // context seq
constexpr int CC = 1024;   // channels
constexpr int CH = 16;     // heads
constexpr int CD = 64;     // head dim

// Scratch (device globals: allocation-free rule)
__device__ float g_q[(size_t)CB * CN * CC];          // 32 MB
__device__ float g_kv[(size_t)CB * CM * 2 * CC];     // 64 MB
__device__ float g_attn[(size_t)CB * CN * CC];       // 32 MB

// ----------------------------------------------------------------------------
// NT SGEMM: C[M,N] = A[M,K] * B[N,K]^T (+ optional bias[n])
// 128x128 tile, BK=16, 256 threads, 8x8 micro-tile per thread.
// A/B staged transposed in smem for conflict-free fragment loads.
// Assumes M%128==0, N%128==0, K%16==0 (true for all calls here).
// ----------------------------------------------------------------------------
__global__ void __launch_bounds__(256) sgemm_nt_kernel(
    const float* __restrict__ A, const float* __restrict__ Bm,
    float* __restrict__ C, int M, int N, int K, const float* __restrict__ bias)
{
    constexpr int BM = 128, BN = 128, BK = 16;
    __shared__ float As[BK][BM];
    __shared__ float Bs[BK][BN];

    const int tid = threadIdx.x;
    const int tx = tid & 15;        // 0..15 -> column micro-block
    const int ty = tid >> 4;        // 0..15 -> row micro-block
    const int m0 = blockIdx.y * BM;
    const int n0 = blockIdx.x * BN;

    float acc[8][8];
#pragma unroll
    for (int i = 0; i < 8; i++)
#pragma unroll
        for (int j = 0; j < 8; j++) acc[i][j] = 0.f;

    for (int k0 = 0; k0 < K; k0 += BK) {
        // Load 128x16 tiles of A and B as float4 along K, store transposed.
#pragma unroll
        for (int l = 0; l < 2; l++) {
            int idx = tid + l * 256;          // 0..511 float4 slots
            int row = idx >> 2;               // 0..127
            int kc  = (idx & 3) << 2;         // 0,4,8,12
            float4 va = *(const float4*)(A + (size_t)(m0 + row) * K + k0 + kc);
            As[kc + 0][row] = va.x; As[kc + 1][row] = va.y;
            As[kc + 2][row] = va.z; As[kc + 3][row] = va.w;
            float4 vb = *(const float4*)(Bm + (size_t)(n0 + row) * K + k0 + kc);
            Bs[kc + 0][row] = vb.x; Bs[kc + 1][row] = vb.y;
            Bs[kc + 2][row] = vb.z; Bs[kc + 3][row] = vb.w;
        }
        __syncthreads();

#pragma unroll
        for (int k = 0; k < BK; k++) {
            float a[8], b[8];
#pragma unroll
            for (int i = 0; i < 8; i++) a[i] = As[k][ty * 8 + i];
#pragma unroll
            for (int j = 0; j < 8; j++) b[j] = Bs[k][tx * 8 + j];
#pragma unroll
            for (int i = 0; i < 8; i++)
#pragma unroll
                for (int j = 0; j < 8; j++)
                    acc[i][j] += a[i] * b[j];
        }
        __syncthreads();
    }

#pragma unroll
    for (int i = 0; i < 8; i++) {
        size_t crow = (size_t)(m0 + ty * 8 + i) * N + n0 + tx * 8;
#pragma unroll
        for (int j = 0; j < 8; j++) {
            float v = acc[i][j];
            if (bias) v += bias[n0 + tx * 8 + j];
            C[crow + j] = v;
        }
    }
}

// ----------------------------------------------------------------------------
// RoPE (in place). Applies to the first 1024 columns of each row.
// rows = B*S; rowstride = 1024 (q) or 2048 (kv -> only k half touched).
// freqs_cis layout: [2048][32][2], fc[n*64 + d2*2 + {0,1}].
// ----------------------------------------------------------------------------
__global__ void rope_kernel(float* __restrict__ x, const float* __restrict__ fc,
                            int rows, int rowstride)
{
    int id = blockIdx.x * blockDim.x + threadIdx.x;
    if (id >= rows * 512) return;
    int row = id >> 9;          // /512 pairs per row
    int w   = id & 511;         // pair index: h*32 + d2
    int n   = row & (CN - 1);   // seq position (S == 2048)
    float* p = x + (size_t)row * rowstride + w * 2;
    float2 v = *(float2*)p;
    float2 f = *(const float2*)(fc + n * 64 + (w & 31) * 2);
    float2 r;
    r.x = v.x * f.x - v.y * f.y;
    r.y = v.y * f.x + v.x * f.y;
    *(float2*)p = r;
}

// ----------------------------------------------------------------------------
// Flash attention, fp32, online softmax.
// Grid: (N/64, H, B), 256 threads. Per CTA: 64 q-rows of one (b,h).
// smem: Qs[64][65] (pre-scaled), KPs[64][65] (K tile, then P), Vs[64][68],
//       m/l/alpha rows.
// Thread (tx,ty) owns a 4x4 micro-tile of the 64x64 S / O tiles.
// ----------------------------------------------------------------------------
constexpr int FS_Q = 64 * 65;
constexpr int FS_K = 64 * 65;
constexpr int FS_V = 64 * 68;
constexpr int FLASH_SMEM = (FS_Q + FS_K + FS_V + 192) * 4;  // 51456 B

__global__ void __launch_bounds__(256) flash_kernel(
    const float* __restrict__ q, const float* __restrict__ kv,
    float* __restrict__ outp)
{
    extern __shared__ float sm[];
    float (*Qs)[65]  = (float(*)[65])sm;
    float (*KPs)[65] = (float(*)[65])(sm + FS_Q);
    float (*Vs)[68]  = (float(*)[68])(sm + FS_Q + FS_K);
    float* mrow = sm + FS_Q + FS_K + FS_V;
    float* lrow = mrow + 64;
    float* arow = lrow + 64;

    const int tid = threadIdx.x;
    const int tx = tid & 15, ty = tid >> 4;
    const int nt = blockIdx.x, h = blockIdx.y, b = blockIdx.z;

    const float* qbase = q  + (size_t)(b * CN + nt * 64) * CC + h * CD;
    const float* kvb   = kv + (size_t)b * CM * (2 * CC) + h * CD;

    // Load + pre-scale Q tile (64 x 64)
#pragma unroll
    for (int l = 0; l < 4; l++) {
        int idx = tid + l * 256;          // 0..1023 float4 slots
        int r  = idx >> 4;                // 0..63
        int dc = (idx & 15) << 2;         // 0..60
        float4 v = *(const float4*)(qbase + (size_t)r * CC + dc);
        Qs[r][dc + 0] = v.x * 0.125f; Qs[r][dc + 1] = v.y * 0.125f;
        Qs[r][dc + 2] = v.z * 0.125f; Qs[r][dc + 3] = v.w * 0.125f;
    }
    if (tid < 64) { mrow[tid] = -1e30f; lrow[tid] = 0.f; }

    float oacc[4][4];
#pragma unroll
    for (int i = 0; i < 4; i++)
#pragma unroll
        for (int j = 0; j < 4; j++) oacc[i][j] = 0.f;

    __syncthreads();

    for (int jt = 0; jt < CM / 64; jt++) {
        // Load K and V tiles (64 x 64 each)
#pragma unroll
        for (int l = 0; l < 4; l++) {
            int idx = tid + l * 256;
            int r  = idx >> 4;
            int dc = (idx & 15) << 2;
            const float* p = kvb + (size_t)(jt * 64 + r) * (2 * CC) + dc;
            float4 kk = *(const float4*)p;
            KPs[r][dc + 0] = kk.x; KPs[r][dc + 1] = kk.y;
            KPs[r][dc + 2] = kk.z; KPs[r][dc + 3] = kk.w;
            float4 vv = *(const float4*)(p + CC);
            Vs[r][dc + 0] = vv.x; Vs[r][dc + 1] = vv.y;
            Vs[r][dc + 2] = vv.z; Vs[r][dc + 3] = vv.w;
        }
        __syncthreads();

        // S = Q * K^T (pre-scaled), 4x4 per thread
        float s[4][4];
#pragma unroll
        for (int i = 0; i < 4; i++)
#pragma unroll
            for (int j = 0; j < 4; j++) s[i][j] = 0.f;
#pragma unroll
        for (int d = 0; d < 64; d++) {
            float a[4], bb[4];
#pragma unroll
            for (int i = 0; i < 4; i++) a[i] = Qs[ty * 4 + i][d];
#pragma unroll
            for (int j = 0; j < 4; j++) bb[j] = KPs[tx * 4 + j][d];
#pragma unroll
            for (int i = 0; i < 4; i++)
#pragma unroll
                for (int j = 0; j < 4; j++)
                    s[i][j] += a[i] * bb[j];
        }
        __syncthreads();   // done reading K; KPs becomes P

#pragma unroll
        for (int i = 0; i < 4; i++)
#pragma unroll
            for (int j = 0; j < 4; j++)
                KPs[ty * 4 + i][tx * 4 + j] = s[i][j];
        __syncthreads();

        // Online softmax: 4 threads per row, 16 cols each
        {
            int r  = tid >> 2;
            int c0 = (tid & 3) << 4;
            float mx = -1e30f;
#pragma unroll
            for (int c = 0; c < 16; c++) mx = fmaxf(mx, KPs[r][c0 + c]);
            mx = fmaxf(mx, __shfl_xor_sync(0xffffffffu, mx, 1));
            mx = fmaxf(mx, __shfl_xor_sync(0xffffffffu, mx, 2));
            float mold = mrow[r];
            float mnew = fmaxf(mold, mx);
            float ps = 0.f;
#pragma unroll
            for (int c = 0; c < 16; c++) {
                float pv = __expf(KPs[r][c0 + c] - mnew);
                KPs[r][c0 + c] = pv;
                ps += pv;
            }
            ps += __shfl_xor_sync(0xffffffffu, ps, 1);
            ps += __shfl_xor_sync(0xffffffffu, ps, 2);
            if ((tid & 3) == 0) {
                float al = __expf(mold - mnew);
                arow[r] = al;
                lrow[r] = lrow[r] * al + ps;
                mrow[r] = mnew;
            }
        }
        __syncthreads();

        // Rescale O, then O += P * V
#pragma unroll
        for (int i = 0; i < 4; i++) {
            float al = arow[ty * 4 + i];
#pragma unroll
            for (int j = 0; j < 4; j++) oacc[i][j] *= al;
        }
#pragma unroll
        for (int mm = 0; mm < 64; mm++) {
            float a[4];
#pragma unroll
            for (int i = 0; i < 4; i++) a[i] = KPs[ty * 4 + i][mm];
            float4 bb = *(float4*)&Vs[mm][tx * 4];
#pragma unroll
            for (int i = 0; i < 4; i++) {
                oacc[i][0] += a[i] * bb.x;
                oacc[i][1] += a[i] * bb.y;
                oacc[i][2] += a[i] * bb.z;
                oacc[i][3] += a[i] * bb.w;
            }
        }
        __syncthreads();   // protect KPs/Vs before next tile load
    }

    // Epilogue: divide by l, store [b, n, h, d]
    float* obase = outp + (size_t)(b * CN + nt * 64) * CC + h * CD;
#pragma unroll
    for (int i = 0; i < 4; i++) {
        float inv = 1.f / lrow[ty * 4 + i];
        float4 w4;
        w4.x = oacc[i][0] * inv; w4.y = oacc[i][1] * inv;
        w4.z = oacc[i][2] * inv; w4.w = oacc[i][3] * inv;
        *(float4*)(obase + (size_t)(ty * 4 + i) * CC + tx * 4) = w4;
    }
}

// ----------------------------------------------------------------------------
// Launch
// ----------------------------------------------------------------------------
extern "C" void kernel_launch(void* const* d_in, const int* in_sizes, int n_in,
                              void* d_out, int out_size)
{
    const float* x     = (const float*)d_in[0];
    const float* ctx   = (const float*)d_in[1];
    const float* fc    = (const float*)d_in[2];
    const float* Wq    = (const float*)d_in[3];
    const float* Wkv   = (const float*)d_in[4];
    const float* Wproj = (const float*)d_in[5];
    const float* bproj = (const float*)d_in[6];
    float* out = (float*)d_out;

    float *q, *kvp, *attn;
    cudaGetSymbolAddress((void**)&q,    g_q);
    cudaGetSymbolAddress((void**)&kvp,  g_kv);
    cudaGetSymbolAddress((void**)&attn, g_attn);

    // Opt-in dynamic smem for the flash kernel (>48KB). Idempotent, host-side.
    cudaFuncSetAttribute(flash_kernel,
                         cudaFuncAttributeMaxDynamicSharedMemorySize, 64 * 1024);

    // 1) q = x @ Wq^T          (8192 x 1024 x 1024)
    sgemm_nt_kernel<<<dim3(CC / 128, (CB * CN) / 128), 256>>>(
        x, Wq, q, CB * CN, CC, CC, nullptr);

    // 2) kv = context @ Wkv^T  (8192 x 2048 x 1024)
    sgemm_nt_kernel<<<dim3((2 * CC) / 128, (CB * CM) / 128), 256>>>(
        ctx, Wkv, kvp, CB * CM, 2 * CC, CC, nullptr);

    // 3) RoPE on q and on k half of kv
    {
        int tq = CB * CN * 512;
        rope_kernel<<<(tq + 255) / 256, 256>>>(q, fc, CB * CN, CC);
        int tk = CB * CM * 512;
        rope_kernel<<<(tk + 255) / 256, 256>>>(kvp, fc, CB * CM, 2 * CC);
    }

    // 4) attention
    flash_kernel<<<dim3(CN / 64, CH, CB), 256, FLASH_SMEM>>>(q, kvp, attn);

    // 5) out = attn @ Wproj^T + bproj
    sgemm_nt_kernel<<<dim3(CC / 128, (CB * CN) / 128), 256>>>(
        attn, Wproj, out, CB * CN, CC, CC, bproj);
}

// round 4
// speedup vs baseline: 1.3690x; 1.3690x over previous
#include <cuda_runtime.h>
#include <cuda_bf16.h>
#include <cstdint>

// Problem constants
constexpr int CB = 4;      // batch
constexpr int CN = 2048;   // query seq
constexpr int CM = 2048;   // context seq
constexpr int CC = 1024;   // channels
constexpr int CH = 16;     // heads
constexpr int CD = 64;     // head dim

// Scratch (device globals: allocation-free rule)
__device__ float g_q[(size_t)CB * CN * CC];          // 32 MB
__device__ float g_kv[(size_t)CB * CM * 2 * CC];     // 64 MB
__device__ float g_attn[(size_t)CB * CN * CC];       // 32 MB

// ============================================================================
// mma.sync m16n8k16 bf16 -> f32 (available on base sm_100 target)
// ============================================================================
__device__ __forceinline__ void mma16816(float* d,
    uint32_t a0, uint32_t a1, uint32_t a2, uint32_t a3,
    uint32_t b0, uint32_t b1)
{
    asm volatile(
        "mma.sync.aligned.m16n8k16.row.col.f32.bf16.bf16.f32 "
        "{%0,%1,%2,%3}, {%4,%5,%6,%7}, {%8,%9}, {%0,%1,%2,%3};"
        : "+f"(d[0]), "+f"(d[1]), "+f"(d[2]), "+f"(d[3])
        : "r"(a0), "r"(a1), "r"(a2), "r"(a3), "r"(b0), "r"(b1));
}

// convert 8 consecutive floats -> packed hi/lo bf16 (uint4 each)
__device__ __forceinline__ void cvt8_split(const float* g, uint4& hi, uint4& lo) {
    float f[8];
    float4 a = *(const float4*)g;
    float4 b = *(const float4*)(g + 4);
    f[0]=a.x; f[1]=a.y; f[2]=a.z; f[3]=a.w;
    f[4]=b.x; f[5]=b.y; f[6]=b.z; f[7]=b.w;
    union { __nv_bfloat162 h2[4]; uint4 u; } Uh, Ul;
#pragma unroll
    for (int j = 0; j < 4; j++) {
        __nv_bfloat16 h0 = __float2bfloat16(f[2*j]);
        __nv_bfloat16 h1 = __float2bfloat16(f[2*j+1]);
        __nv_bfloat16 l0 = __float2bfloat16(f[2*j]   - __bfloat162float(h0));
        __nv_bfloat16 l1 = __float2bfloat16(f[2*j+1] - __bfloat162float(h1));
        Uh.h2[j] = __halves2bfloat162(h0, h1);
        Ul.h2[j] = __halves2bfloat162(l0, l1);
    }
    hi = Uh.u; lo = Ul.u;
}

// ============================================================================
// NT GEMM via mma.sync with bf16-split (3-term) fp32 emulation.
// C[M,N] = A[M,K] * B[N,K]^T (+ optional bias[n]).
// CTA tile 128x128, BK=32, 256 threads (8 warps, 4x2 grid, 32x64 per warp).
// smem rows padded to 20 b32 (80B): conflict-free fragment loads + 16B stores.
// Requires M%128==0, N%128==0, K%32==0.
// ============================================================================
constexpr int GS = 20;               // b32 stride per smem row
constexpr int GT_ROWS = 128;         // rows per tile
constexpr int GT_TSZ = GT_ROWS * GS; // b32 per tile (2560)

__global__ void __launch_bounds__(256) gemm_mma_kernel(
    const float* __restrict__ A, const float* __restrict__ Bm,
    float* __restrict__ C, int M, int N, int K, const float* __restrict__ bias)
{
    __shared__ uint32_t sm[4 * GT_TSZ];   // Ahi, Alo, Bhi, Blo  (40 KB)
    uint32_t* sAhi = sm;
    uint32_t* sAlo = sm + GT_TSZ;
    uint32_t* sBhi = sm + 2 * GT_TSZ;
    uint32_t* sBlo = sm + 3 * GT_TSZ;

    const int tid = threadIdx.x;
    const int wid = tid >> 5;
    const int lane = tid & 31;
    const int warp_m = wid & 3;          // 4 warps over 128 rows
    const int warp_n = wid >> 2;         // 2 warps over 128 cols
    const int m0 = blockIdx.y * 128;
    const int n0 = blockIdx.x * 128;

    float acc[2][8][4];
#pragma unroll
    for (int i = 0; i < 2; i++)
#pragma unroll
        for (int j = 0; j < 8; j++)
#pragma unroll
            for (int q = 0; q < 4; q++) acc[i][j][q] = 0.f;

    const int lr = tid >> 1;          // load row 0..127
    const int lh = tid & 1;           // half: cols 0-15 or 16-31

    for (int k0 = 0; k0 < K; k0 += 32) {
        // ---- load + split-convert A and B tiles (128 x 32 fp32 each) ----
        {
            const float* ap = A + (size_t)(m0 + lr) * K + k0 + lh * 16;
            uint4 h0, l0, h1, l1;
            cvt8_split(ap, h0, l0);
            cvt8_split(ap + 8, h1, l1);
            int o = lr * GS + lh * 8;
            *(uint4*)(sAhi + o)     = h0;  *(uint4*)(sAhi + o + 4) = h1;
            *(uint4*)(sAlo + o)     = l0;  *(uint4*)(sAlo + o + 4) = l1;
            const float* bp = Bm + (size_t)(n0 + lr) * K + k0 + lh * 16;
            cvt8_split(bp, h0, l0);
            cvt8_split(bp + 8, h1, l1);
            *(uint4*)(sBhi + o)     = h0;  *(uint4*)(sBhi + o + 4) = h1;
            *(uint4*)(sBlo + o)     = l0;  *(uint4*)(sBlo + o + 4) = l1;
        }
        __syncthreads();

        // ---- 3 terms: hi*hi, hi*lo, lo*hi ----
#pragma unroll
        for (int t = 0; t < 3; t++) {
            const uint32_t* As = (t < 2) ? sAhi : sAlo;
            const uint32_t* Bs = (t == 1) ? sBlo : sBhi;
#pragma unroll
            for (int ks = 0; ks < 2; ks++) {
                const int ac = (lane & 3) + ks * 8;
                const int ar = warp_m * 32 + (lane >> 2);
                uint32_t a[2][4];
#pragma unroll
                for (int i = 0; i < 2; i++) {
                    int r = ar + i * 16;
                    a[i][0] = As[r * GS + ac];
                    a[i][1] = As[(r + 8) * GS + ac];
                    a[i][2] = As[r * GS + ac + 4];
                    a[i][3] = As[(r + 8) * GS + ac + 4];
                }
#pragma unroll
                for (int j = 0; j < 8; j++) {
                    int br = warp_n * 64 + j * 8 + (lane >> 2);
                    uint32_t b0 = Bs[br * GS + ac];
                    uint32_t b1 = Bs[br * GS + ac + 4];
                    mma16816(acc[0][j], a[0][0], a[0][1], a[0][2], a[0][3], b0, b1);
                    mma16816(acc[1][j], a[1][0], a[1][1], a[1][2], a[1][3], b0, b1);
                }
            }
        }
        __syncthreads();
    }

    // ---- epilogue ----
#pragma unroll
    for (int i = 0; i < 2; i++) {
        int row = m0 + warp_m * 32 + i * 16 + (lane >> 2);
#pragma unroll
        for (int j = 0; j < 8; j++) {
            int col = n0 + warp_n * 64 + j * 8 + (lane & 3) * 2;
            float2 w0, w1;
            w0.x = acc[i][j][0]; w0.y = acc[i][j][1];
            w1.x = acc[i][j][2]; w1.y = acc[i][j][3];
            if (bias) {
                float2 bb = *(const float2*)(bias + col);
                w0.x += bb.x; w0.y += bb.y;
                w1.x += bb.x; w1.y += bb.y;
            }
            *(float2*)(C + (size_t)row * N + col) = w0;
            *(float2*)(C + (size_t)(row + 8) * N + col) = w1;
        }
    }
}

// ----------------------------------------------------------------------------
// RoPE (in place). Applies to the first 1024 columns of each row.
// ----------------------------------------------------------------------------
__global__ void rope_kernel(float* __restrict__ x, const float* __restrict__ fc,
                            int rows, int rowstride)
{
    int id = blockIdx.x * blockDim.x + threadIdx.x;
    if (id >= rows * 512) return;
    int row = id >> 9;
    int w   = id & 511;
    int n   = row & (CN - 1);
    float* p = x + (size_t)row * rowstride + w * 2;
    float2 v = *(float2*)p;
    float2 f = *(const float2*)(fc + n * 64 + (w & 31) * 2);
    float2 r;
    r.x = v.x * f.x - v.y * f.y;
    r.y = v.y * f.x + v.x * f.y;
    *(float2*)p = r;
}

// ----------------------------------------------------------------------------
// Flash attention, fp32, online softmax (unchanged — known good).
// ----------------------------------------------------------------------------
constexpr int FS_Q = 64 * 65;
constexpr int FS_K = 64 * 65;
constexpr int FS_V = 64 * 68;
constexpr int FLASH_SMEM = (FS_Q + FS_K + FS_V + 192) * 4;

__global__ void __launch_bounds__(256) flash_kernel(
    const float* __restrict__ q, const float* __restrict__ kv,
    float* __restrict__ outp)
{
    extern __shared__ float sm[];
    float (*Qs)[65]  = (float(*)[65])sm;
    float (*KPs)[65] = (float(*)[65])(sm + FS_Q);
    float (*Vs)[68]  = (float(*)[68])(sm + FS_Q + FS_K);
    float* mrow = sm + FS_Q + FS_K + FS_V;
    float* lrow = mrow + 64;
    float* arow = lrow + 64;

    const int tid = threadIdx.x;
    const int tx = tid & 15, ty = tid >> 4;
    const int nt = blockIdx.x, h = blockIdx.y, b = blockIdx.z;

    const float* qbase = q  + (size_t)(b * CN + nt * 64) * CC + h * CD;
    const float* kvb   = kv + (size_t)b * CM * (2 * CC) + h * CD;

#pragma unroll
    for (int l = 0; l < 4; l++) {
        int idx = tid + l * 256;
        int r  = idx >> 4;
        int dc = (idx & 15) << 2;
        float4 v = *(const float4*)(qbase + (size_t)r * CC + dc);
        Qs[r][dc + 0] = v.x * 0.125f; Qs[r][dc + 1] = v.y * 0.125f;
        Qs[r][dc + 2] = v.z * 0.125f; Qs[r][dc + 3] = v.w * 0.125f;
    }
    if (tid < 64) { mrow[tid] = -1e30f; lrow[tid] = 0.f; }

    float oacc[4][4];
#pragma unroll
    for (int i = 0; i < 4; i++)
#pragma unroll
        for (int j = 0; j < 4; j++) oacc[i][j] = 0.f;

    __syncthreads();

    for (int jt = 0; jt < CM / 64; jt++) {
#pragma unroll
        for (int l = 0; l < 4; l++) {
            int idx = tid + l * 256;
            int r  = idx >> 4;
            int dc = (idx & 15) << 2;
            const float* p = kvb + (size_t)(jt * 64 + r) * (2 * CC) + dc;
            float4 kk = *(const float4*)p;
            KPs[r][dc + 0] = kk.x; KPs[r][dc + 1] = kk.y;
            KPs[r][dc + 2] = kk.z; KPs[r][dc + 3] = kk.w;
            float4 vv = *(const float4*)(p + CC);
            Vs[r][dc + 0] = vv.x; Vs[r][dc + 1] = vv.y;
            Vs[r][dc + 2] = vv.z; Vs[r][dc + 3] = vv.w;
        }
        __syncthreads();

        float s[4][4];
#pragma unroll
        for (int i = 0; i < 4; i++)
#pragma unroll
            for (int j = 0; j < 4; j++) s[i][j] = 0.f;
#pragma unroll
        for (int d = 0; d < 64; d++) {
            float a[4], bb[4];
#pragma unroll
            for (int i = 0; i < 4; i++) a[i] = Qs[ty * 4 + i][d];
#pragma unroll
            for (int j = 0; j < 4; j++) bb[j] = KPs[tx * 4 + j][d];
#pragma unroll
            for (int i = 0; i < 4; i++)
#pragma unroll
                for (int j = 0; j < 4; j++)
                    s[i][j] += a[i] * bb[j];
        }
        __syncthreads();

#pragma unroll
        for (int i = 0; i < 4; i++)
#pragma unroll
            for (int j = 0; j < 4; j++)
                KPs[ty * 4 + i][tx * 4 + j] = s[i][j];
        __syncthreads();

        {
            int r  = tid >> 2;
            int c0 = (tid & 3) << 4;
            float mx = -1e30f;
#pragma unroll
            for (int c = 0; c < 16; c++) mx = fmaxf(mx, KPs[r][c0 + c]);
            mx = fmaxf(mx, __shfl_xor_sync(0xffffffffu, mx, 1));
            mx = fmaxf(mx, __shfl_xor_sync(0xffffffffu, mx, 2));
            float mold = mrow[r];
            float mnew = fmaxf(mold, mx);
            float ps = 0.f;
#pragma unroll
            for (int c = 0; c < 16; c++) {
                float pv = __expf(KPs[r][c0 + c] - mnew);
                KPs[r][c0 + c] = pv;
                ps += pv;
            }
            ps += __shfl_xor_sync(0xffffffffu, ps, 1);
            ps += __shfl_xor_sync(0xffffffffu, ps, 2);
            if ((tid & 3) == 0) {
                float al = __expf(mold - mnew);
                arow[r] = al;
                lrow[r] = lrow[r] * al + ps;
                mrow[r] = mnew;
            }
        }
        __syncthreads();

#pragma unroll
        for (int i = 0; i < 4; i++) {
            float al = arow[ty * 4 + i];
#pragma unroll
            for (int j = 0; j < 4; j++) oacc[i][j] *= al;
        }
#pragma unroll
        for (int mm = 0; mm < 64; mm++) {
            float a[4];
#pragma unroll
            for (int i = 0; i < 4; i++) a[i] = KPs[ty * 4 + i][mm];
            float4 bb = *(float4*)&Vs[mm][tx * 4];
#pragma unroll
            for (int i = 0; i < 4; i++) {
                oacc[i][0] += a[i] * bb.x;
                oacc[i][1] += a[i] * bb.y;
                oacc[i][2] += a[i] * bb.z;
                oacc[i][3] += a[i] * bb.w;
            }
        }
        __syncthreads();
    }

    float* obase = outp + (size_t)(b * CN + nt * 64) * CC + h * CD;
#pragma unroll
    for (int i = 0; i < 4; i++) {
        float inv = 1.f / lrow[ty * 4 + i];
        float4 w4;
        w4.x = oacc[i][0] * inv; w4.y = oacc[i][1] * inv;
        w4.z = oacc[i][2] * inv; w4.w = oacc[i][3] * inv;
        *(float4*)(obase + (size_t)(ty * 4 + i) * CC + tx * 4) = w4;
    }
}

// ----------------------------------------------------------------------------
// Launch
// ----------------------------------------------------------------------------
extern "C" void kernel_launch(void* const* d_in, const int* in_sizes, int n_in,
                              void* d_out, int out_size)
{
    const float* x     = (const float*)d_in[0];
    const float* ctx   = (const float*)d_in[1];
    const float* fc    = (const float*)d_in[2];
    const float* Wq    = (const float*)d_in[3];
    const float* Wkv   = (const float*)d_in[4];
    const float* Wproj = (const float*)d_in[5];
    const float* bproj = (const float*)d_in[6];
    float* out = (float*)d_out;

    float *q, *kvp, *attn;
    cudaGetSymbolAddress((void**)&q,    g_q);
    cudaGetSymbolAddress((void**)&kvp,  g_kv);
    cudaGetSymbolAddress((void**)&attn, g_attn);

    cudaFuncSetAttribute(flash_kernel,
                         cudaFuncAttributeMaxDynamicSharedMemorySize, 64 * 1024);

    // 1) q = x @ Wq^T          (8192 x 1024 x 1024)
    gemm_mma_kernel<<<dim3(CC / 128, (CB * CN) / 128), 256>>>(
        x, Wq, q, CB * CN, CC, CC, nullptr);

    // 2) kv = context @ Wkv^T  (8192 x 2048 x 1024)
    gemm_mma_kernel<<<dim3((2 * CC) / 128, (CB * CM) / 128), 256>>>(
        ctx, Wkv, kvp, CB * CM, 2 * CC, CC, nullptr);

    // 3) RoPE on q and on k half of kv
    {
        int tq = CB * CN * 512;
        rope_kernel<<<(tq + 255) / 256, 256>>>(q, fc, CB * CN, CC);
        int tk = CB * CM * 512;
        rope_kernel<<<(tk + 255) / 256, 256>>>(kvp, fc, CB * CM, 2 * CC);
    }

    // 4) attention
    flash_kernel<<<dim3(CN / 64, CH, CB), 256, FLASH_SMEM>>>(q, kvp, attn);

    // 5) out = attn @ Wproj^T + bproj
    gemm_mma_kernel<<<dim3(CC / 128, (CB * CN) / 128), 256>>>(
        attn, Wproj, out, CB * CN, CC, CC, bproj);
}